// round 2
// baseline (speedup 1.0000x reference)
#include <cuda_runtime.h>
#include <math.h>

#define B_ 4096
#define S_ 32
#define F_ 256
#define E_ 256

// ---------------- scratch (__device__ globals; no allocations) ----------------
__device__ float SC_m   [B_ * F_];        // mean neighbor feats
__device__ float SC_self[B_ * F_];        // self feats
__device__ float SC_Q   [B_ * E_];        // query
__device__ float SC_t   [B_ * F_];        // t = Wk @ Q  (per row)
__device__ float SC_y   [B_ * F_];        // attn-weighted feature sum
__device__ float SC_Z   [B_ * 2 * E_];    // [mix | ctx]
__device__ float SC_P   [B_ * E_];        // pre-activation of final layer

// ---------------- kernel 1: gather self + mean of mean-neighbors --------------
__global__ void __launch_bounds__(256) k_gather(const int* __restrict__ nodes,
                                                const int* __restrict__ neigh,
                                                const float* __restrict__ feat)
{
    const int b = blockIdx.x;
    const int f = threadIdx.x;  // 256

    __shared__ int idx[S_];
    if (f < S_) idx[f] = neigh[b * S_ + f];
    SC_self[b * F_ + f] = feat[nodes[b] * F_ + f];
    __syncthreads();

    float acc = 0.f;
#pragma unroll
    for (int s = 0; s < S_; s++)
        acc += feat[idx[s] * F_ + f];
    SC_m[b * F_ + f] = acc * (1.0f / S_);
}

// ---------------- generic fp32 tiled GEMM: C[M,256] = A[M,K] @ W (+bias) ------
// BM=128, BN=64, BK=16, 256 threads, 8x4 per thread.
// TRANSB=false: W is [K,256] row-major. TRANSB=true: W is [256,K] row-major (B^T).
template <bool TRANSB>
__device__ __forceinline__ void gemm_tile(const float* __restrict__ A,
                                          const float* __restrict__ W,
                                          const float* __restrict__ bias,
                                          float* __restrict__ C,
                                          int K, int ldc)
{
    constexpr int N = 256;
    __shared__ float As[16][128];
    __shared__ float Bs[16][64];

    const int tid = threadIdx.x;
    const int bm = blockIdx.y * 128;
    const int bn = blockIdx.x * 64;
    const int tx = tid & 15;   // n
    const int ty = tid >> 4;   // m
    const int ar = tid >> 2;          // 0..63 (A row within tile, +64 for second)
    const int ac = (tid & 3) << 2;    // 0,4,8,12

    const float* Ap  = A + (bm + ar) * K + ac;
    const float* Ap2 = Ap + 64 * K;

    float4 a0 = *(const float4*)Ap;
    float4 a1 = *(const float4*)Ap2;
    float4 b0;
    if (!TRANSB) b0 = *(const float4*)(W + (tid >> 4) * N + bn + ((tid & 15) << 2));
    else         b0 = *(const float4*)(W + (bn + (tid >> 2)) * K + ((tid & 3) << 2));

    float acc[8][4] = {};

    int k0 = 0;
    while (true) {
        // store prefetched tile to smem
        As[ac + 0][ar] = a0.x; As[ac + 1][ar] = a0.y;
        As[ac + 2][ar] = a0.z; As[ac + 3][ar] = a0.w;
        As[ac + 0][ar + 64] = a1.x; As[ac + 1][ar + 64] = a1.y;
        As[ac + 2][ar + 64] = a1.z; As[ac + 3][ar + 64] = a1.w;
        if (!TRANSB) {
            *(float4*)&Bs[tid >> 4][(tid & 15) << 2] = b0;
        } else {
            const int kk = (tid & 3) << 2, nn = tid >> 2;
            Bs[kk + 0][nn] = b0.x; Bs[kk + 1][nn] = b0.y;
            Bs[kk + 2][nn] = b0.z; Bs[kk + 3][nn] = b0.w;
        }
        __syncthreads();

        k0 += 16;
        const bool more = (k0 < K);
        if (more) {
            a0 = *(const float4*)(Ap + k0);
            a1 = *(const float4*)(Ap2 + k0);
            if (!TRANSB) b0 = *(const float4*)(W + (k0 + (tid >> 4)) * N + bn + ((tid & 15) << 2));
            else         b0 = *(const float4*)(W + (bn + (tid >> 2)) * K + k0 + ((tid & 3) << 2));
        }

#pragma unroll
        for (int k = 0; k < 16; k++) {
            float a[8], b[4];
            *(float4*)&a[0] = *(const float4*)&As[k][ty * 8];
            *(float4*)&a[4] = *(const float4*)&As[k][ty * 8 + 4];
            *(float4*)&b[0] = *(const float4*)&Bs[k][tx * 4];
#pragma unroll
            for (int i = 0; i < 8; i++)
#pragma unroll
                for (int j = 0; j < 4; j++)
                    acc[i][j] += a[i] * b[j];
        }
        __syncthreads();
        if (!more) break;
    }

    float4 bb = make_float4(0.f, 0.f, 0.f, 0.f);
    if (bias) bb = *(const float4*)&bias[bn + tx * 4];
#pragma unroll
    for (int i = 0; i < 8; i++) {
        const int row = bm + ty * 8 + i;
        float4 v;
        v.x = acc[i][0] + bb.x; v.y = acc[i][1] + bb.y;
        v.z = acc[i][2] + bb.z; v.w = acc[i][3] + bb.w;
        *(float4*)&C[row * ldc + bn + tx * 4] = v;
    }
}

__global__ void __launch_bounds__(256) k_gemm(const float* __restrict__ A,
                                              const float* __restrict__ W,
                                              const float* __restrict__ bias,
                                              float* __restrict__ C, int K, int ldc)
{
    gemm_tile<false>(A, W, bias, C, K, ldc);
}

__global__ void __launch_bounds__(256) k_gemm_tb(const float* __restrict__ A,
                                                 const float* __restrict__ W,
                                                 float* __restrict__ C, int K, int ldc)
{
    gemm_tile<true>(A, W, nullptr, C, K, ldc);
}

// two independent GEMMs fused over blockIdx.z to fill the chip in one wave
__global__ void __launch_bounds__(256) k_gemm_dual(
    const float* __restrict__ A0, const float* __restrict__ W0,
    const float* __restrict__ b0, float* __restrict__ C0, int ldc0,
    const float* __restrict__ A1, const float* __restrict__ W1,
    const float* __restrict__ b1, float* __restrict__ C1, int ldc1)
{
    if (blockIdx.z == 0) gemm_tile<false>(A0, W0, b0, C0, 256, ldc0);
    else                 gemm_tile<false>(A1, W1, b1, C1, 256, ldc1);
}

// ---------------- kernel: attention (scores, softmax, weighted feature sum) ---
__global__ void __launch_bounds__(256) k_attn(const int* __restrict__ neigh,
                                              const float* __restrict__ feat)
{
    const int b = blockIdx.x;
    const int tid = threadIdx.x;

    __shared__ float Xs[S_][F_];
    __shared__ float ts[F_];
    __shared__ float sc[S_];
    __shared__ int   idx[S_];

    ts[tid] = SC_t[b * F_ + tid];
    if (tid < S_) idx[tid] = neigh[b * S_ + tid];
    __syncthreads();

    // load 32 neighbor rows (32 KB) into smem via float4
#pragma unroll
    for (int i = 0; i < 8; i++) {
        const int e = i * 256 + tid;          // 0..2047 float4 slots
        const int s = e >> 6, c = (e & 63) << 2;
        *(float4*)&Xs[s][c] = *(const float4*)&feat[idx[s] * F_ + c];
    }
    __syncthreads();

    // scores: 8 warps x 4 rows, dot(X_s, t) over 256
    const int wid = tid >> 5, lane = tid & 31;
#pragma unroll
    for (int r = 0; r < 4; r++) {
        const int s = wid * 4 + r;
        float p = 0.f;
#pragma unroll
        for (int j = 0; j < 8; j++)
            p += Xs[s][lane + 32 * j] * ts[lane + 32 * j];
#pragma unroll
        for (int o = 16; o; o >>= 1) p += __shfl_xor_sync(0xffffffffu, p, o);
        if (lane == 0) sc[s] = p;
    }
    __syncthreads();

    // softmax over 32 (self slot masked out by construction)
    if (tid < 32) {
        float v = sc[tid];
        float mx = v;
#pragma unroll
        for (int o = 16; o; o >>= 1) mx = fmaxf(mx, __shfl_xor_sync(0xffffffffu, mx, o));
        float e = expf(v - mx);
        float sum = e;
#pragma unroll
        for (int o = 16; o; o >>= 1) sum += __shfl_xor_sync(0xffffffffu, sum, o);
        sc[tid] = e / sum;
    }
    __syncthreads();

    // y[f] = sum_s a_s * X[s][f]
    float acc = 0.f;
#pragma unroll
    for (int s = 0; s < S_; s++)
        acc += sc[s] * Xs[s][tid];
    SC_y[b * F_ + tid] = acc;
}

// ---------------- kernel: tanh + L2 normalize ---------------------------------
__global__ void __launch_bounds__(256) k_norm(float* __restrict__ out)
{
    const int b = blockIdx.x, tid = threadIdx.x;
    const float v = tanhf(SC_P[b * E_ + tid]);
    float ss = v * v;
    const int lane = tid & 31, wid = tid >> 5;
#pragma unroll
    for (int o = 16; o; o >>= 1) ss += __shfl_xor_sync(0xffffffffu, ss, o);
    __shared__ float red[8];
    if (lane == 0) red[wid] = ss;
    __syncthreads();
    float tot = 0.f;
#pragma unroll
    for (int i = 0; i < 8; i++) tot += red[i];
    const float scale = 1.0f / fmaxf(sqrtf(tot), 1e-12f);
    out[b * E_ + tid] = v * scale;
}

// ---------------- host ---------------------------------------------------------
extern "C" void kernel_launch(void* const* d_in, const int* in_sizes, int n_in,
                              void* d_out, int out_size)
{
    const int*   nodes  = (const int*)  d_in[0];
    const int*   n_mean = (const int*)  d_in[1];
    const int*   n_attn = (const int*)  d_in[2];
    const float* feat   = (const float*)d_in[3];
    const float* Wm = (const float*)d_in[4],  *bm = (const float*)d_in[5];
    const float* Wq = (const float*)d_in[6],  *bq = (const float*)d_in[7];
    const float* Wk = (const float*)d_in[8];  // bk (d_in[9]) cancels in softmax
    const float* Wv = (const float*)d_in[10], *bv = (const float*)d_in[11];
    const float* Wc = (const float*)d_in[12], *bc = (const float*)d_in[13];
    float* out = (float*)d_out;

    float *p_m, *p_self, *p_Q, *p_t, *p_y, *p_Z, *p_P;
    cudaGetSymbolAddress((void**)&p_m,    SC_m);
    cudaGetSymbolAddress((void**)&p_self, SC_self);
    cudaGetSymbolAddress((void**)&p_Q,    SC_Q);
    cudaGetSymbolAddress((void**)&p_t,    SC_t);
    cudaGetSymbolAddress((void**)&p_y,    SC_y);
    cudaGetSymbolAddress((void**)&p_Z,    SC_Z);
    cudaGetSymbolAddress((void**)&p_P,    SC_P);

    const dim3 gemm_grid(E_ / 64, B_ / 128, 1);
    const dim3 gemm_grid2(E_ / 64, B_ / 128, 2);

    // 1) gathers: self feats + mean-aggregator mean
    k_gather<<<B_, 256>>>(nodes, n_mean, feat);

    // 2) ctx = m @ Wm + bm  -> Z[:,256:512];   Q = self @ Wq + bq
    k_gemm_dual<<<gemm_grid2, 256>>>(p_m,    Wm, bm, p_Z + E_, 2 * E_,
                                     p_self, Wq, bq, p_Q,      E_);

    // 3) t = Q @ Wk^T   (Wk stored [F,E]; bk cancels in softmax)
    k_gemm_tb<<<gemm_grid, 256>>>(p_Q, Wk, p_t, /*K=*/E_, /*ldc=*/F_);

    // 4) attention: scores = X·t, softmax over 32 neighbors, y = attn-weighted X
    k_attn<<<B_, 256>>>(n_attn, feat);

    // 5) mix = y @ Wv + bv -> Z[:,0:256]
    k_gemm<<<gemm_grid, 256>>>(p_y, Wv, bv, p_Z, /*K=*/F_, /*ldc=*/2 * E_);

    // 6) P = Z @ Wc + bc   (K = 512)
    k_gemm<<<gemm_grid, 256>>>(p_Z, Wc, bc, p_P, /*K=*/2 * E_, /*ldc=*/E_);

    // 7) out = L2-normalize(tanh(P))
    k_norm<<<B_, 256>>>(out);
}

// round 5
// speedup vs baseline: 1.1667x; 1.1667x over previous
#include <cuda_runtime.h>
#include <cuda_bf16.h>
#include <mma.h>
#include <cstdint>
#include <math.h>

using namespace nvcuda;

#define B_ 4096
#define S_ 32
#define F_ 256
#define E_ 256

#define BM 64
#define BN 128
#define SPAD 24   // bf16 elements per smem row (16 data + 8 pad)

// ======================= scratch (__device__ globals) =======================
__device__ __nv_bfloat16 G_mh[B_ * F_],  G_ml[B_ * F_];     // mean neigh feats
__device__ __nv_bfloat16 G_sh[B_ * F_],  G_sl[B_ * F_];     // self feats
__device__ __nv_bfloat16 G_Qh[B_ * E_],  G_Ql[B_ * E_];     // query
__device__ __nv_bfloat16 G_Yh[B_ * F_],  G_Yl[B_ * F_];     // attn-weighted feats
__device__ __nv_bfloat16 G_Zh[B_ * 2 * E_], G_Zl[B_ * 2 * E_];  // [mix | ctx]
__device__ float SC_t[B_ * F_];          // t[b,f] = sum_e Wk[f,e] Q[b,e]
__device__ float SC_P[B_ * E_];          // final pre-activation

// weights: stored [N][K] (K-major) + hi/lo split
__device__ __nv_bfloat16 G_WmTh[E_ * F_],     G_WmTl[E_ * F_];
__device__ __nv_bfloat16 G_WqTh[E_ * F_],     G_WqTl[E_ * F_];
__device__ __nv_bfloat16 G_WvTh[E_ * F_],     G_WvTl[E_ * F_];
__device__ __nv_bfloat16 G_WcTh[E_ * 2 * E_], G_WcTl[E_ * 2 * E_];
__device__ __nv_bfloat16 G_Wkh[F_ * E_],      G_Wkl[F_ * E_];  // Wk as stored is already [N=F][K=E]

__device__ __forceinline__ void bsplit(float x, __nv_bfloat16& h, __nv_bfloat16& l) {
    h = __float2bfloat16(x);
    l = __float2bfloat16(x - __bfloat162float(h));
}

// ======================= weight prep: transpose + hi/lo split ================
__global__ void __launch_bounds__(256) k_prep(const float* __restrict__ Wm,
                                              const float* __restrict__ Wq,
                                              const float* __restrict__ Wv,
                                              const float* __restrict__ Wc,
                                              const float* __restrict__ Wk)
{
    const int z = blockIdx.z;
    if (z == 4) {  // Wk: straight hi/lo convert of [256][256]
        const int start = (blockIdx.x * 8 + blockIdx.y) * 512 + threadIdx.x;
#pragma unroll
        for (int i = 0; i < 2; i++) {
            const int e = start + i * 256;
            bsplit(Wk[e], G_Wkh[e], G_Wkl[e]);
        }
        return;
    }
    const float* W; __nv_bfloat16 *Oh, *Ol; int K;
    if      (z == 0) { W = Wm; Oh = G_WmTh; Ol = G_WmTl; K = 256; }
    else if (z == 1) { W = Wq; Oh = G_WqTh; Ol = G_WqTl; K = 256; }
    else if (z == 2) { W = Wv; Oh = G_WvTh; Ol = G_WvTl; K = 256; }
    else             { W = Wc; Oh = G_WcTh; Ol = G_WcTl; K = 512; }
    const int k0 = blockIdx.x * 32, n0 = blockIdx.y * 32;
    if (k0 >= K) return;

    const int tx = threadIdx.x & 31, ty = threadIdx.x >> 5;
    __shared__ float tile[32][33];
#pragma unroll
    for (int i = 0; i < 4; i++)
        tile[ty + 8 * i][tx] = W[(size_t)(k0 + ty + 8 * i) * 256 + n0 + tx];
    __syncthreads();
#pragma unroll
    for (int i = 0; i < 4; i++) {
        const int n = n0 + ty + 8 * i, k = k0 + tx;
        bsplit(tile[tx][ty + 8 * i], Oh[(size_t)n * K + k], Ol[(size_t)n * K + k]);
    }
}

// ======================= gather: self feats + mean of mean-neighbors =========
__global__ void __launch_bounds__(256) k_gather(const int* __restrict__ nodes,
                                                const int* __restrict__ neigh,
                                                const float* __restrict__ feat)
{
    const int b = blockIdx.x;
    const int f = threadIdx.x;

    __shared__ int idx[S_];
    if (f < S_) idx[f] = neigh[b * S_ + f];
    bsplit(feat[(size_t)nodes[b] * F_ + f], G_sh[b * F_ + f], G_sl[b * F_ + f]);
    __syncthreads();

    float acc = 0.f;
#pragma unroll
    for (int s = 0; s < S_; s++)
        acc += feat[(size_t)idx[s] * F_ + f];
    bsplit(acc * (1.0f / S_), G_mh[b * F_ + f], G_ml[b * F_ + f]);
}

// ======================= WMMA bf16 hi/lo GEMM ================================
// C[4096, 256] = (Ah+Al)[4096,K] @ (Bh+Bl)^T, B stored [256][K] K-major.
// CTA tile 64x128, 8 warps (2x4), warp tile 32x32 (2x2 wmma frags), BK=16.
__device__ __forceinline__ void wgemm_core(
    const __nv_bfloat16* __restrict__ Ah, const __nv_bfloat16* __restrict__ Al,
    const __nv_bfloat16* __restrict__ Bh, const __nv_bfloat16* __restrict__ Bl,
    const float* __restrict__ bias,
    float* __restrict__ Cf, __nv_bfloat16* __restrict__ Ch, __nv_bfloat16* __restrict__ Cl,
    int K, int ldc, bool bf16out)
{
    __shared__ __align__(32) char smem_raw[BM * BN * 4];  // 32 KB, reused by epilogue
    __nv_bfloat16* sAh = (__nv_bfloat16*)smem_raw;                    // 64*24*2  = 3072 B
    __nv_bfloat16* sAl = sAh + BM * SPAD;                             // +3072
    __nv_bfloat16* sBh = sAl + BM * SPAD;                             // +6144 (128*24*2)
    __nv_bfloat16* sBl = sBh + BN * SPAD;                             // +6144 -> 18432 total
    float* Cs = (float*)smem_raw;

    const int tid = threadIdx.x;
    const int wid = tid >> 5;
    const int wm = wid & 1;        // warp row (2)
    const int wn = wid >> 1;       // warp col (4)
    const int m0 = blockIdx.y * BM;
    const int n0 = blockIdx.x * BN;

    wmma::fragment<wmma::accumulator, 16, 16, 16, float> acc[2][2];
#pragma unroll
    for (int i = 0; i < 2; i++)
#pragma unroll
        for (int j = 0; j < 2; j++)
            wmma::fill_fragment(acc[i][j], 0.0f);

    // global load indices
    const int ar = tid >> 2, ac = (tid & 3) * 4;   // A: 64x16, 4 bf16 per thread
    const int br = tid >> 1, bc = (tid & 1) * 8;   // B: 128x16, 8 bf16 per thread

    for (int k0 = 0; k0 < K; k0 += 16) {
        *(uint2*)&sAh[ar * SPAD + ac] = *(const uint2*)&Ah[(size_t)(m0 + ar) * K + k0 + ac];
        *(uint2*)&sAl[ar * SPAD + ac] = *(const uint2*)&Al[(size_t)(m0 + ar) * K + k0 + ac];
        *(uint4*)&sBh[br * SPAD + bc] = *(const uint4*)&Bh[(size_t)(n0 + br) * K + k0 + bc];
        *(uint4*)&sBl[br * SPAD + bc] = *(const uint4*)&Bl[(size_t)(n0 + br) * K + k0 + bc];
        __syncthreads();

        wmma::fragment<wmma::matrix_a, 16, 16, 16, __nv_bfloat16, wmma::row_major> a_h[2], a_l[2];
        wmma::fragment<wmma::matrix_b, 16, 16, 16, __nv_bfloat16, wmma::col_major> b_h[2], b_l[2];
#pragma unroll
        for (int mi = 0; mi < 2; mi++) {
            wmma::load_matrix_sync(a_h[mi], sAh + (wm * 32 + mi * 16) * SPAD, SPAD);
            wmma::load_matrix_sync(a_l[mi], sAl + (wm * 32 + mi * 16) * SPAD, SPAD);
        }
#pragma unroll
        for (int ni = 0; ni < 2; ni++) {
            wmma::load_matrix_sync(b_h[ni], sBh + (wn * 32 + ni * 16) * SPAD, SPAD);
            wmma::load_matrix_sync(b_l[ni], sBl + (wn * 32 + ni * 16) * SPAD, SPAD);
        }
#pragma unroll
        for (int mi = 0; mi < 2; mi++)
#pragma unroll
            for (int ni = 0; ni < 2; ni++) {
                wmma::mma_sync(acc[mi][ni], a_h[mi], b_h[ni], acc[mi][ni]);
                wmma::mma_sync(acc[mi][ni], a_h[mi], b_l[ni], acc[mi][ni]);
                wmma::mma_sync(acc[mi][ni], a_l[mi], b_h[ni], acc[mi][ni]);
            }
        __syncthreads();
    }

    // epilogue: stage through smem, add bias, write (f32 or bf16 hi/lo)
#pragma unroll
    for (int mi = 0; mi < 2; mi++)
#pragma unroll
        for (int ni = 0; ni < 2; ni++)
            wmma::store_matrix_sync(Cs + (wm * 32 + mi * 16) * BN + wn * 32 + ni * 16,
                                    acc[mi][ni], BN, wmma::mem_row_major);
    __syncthreads();

    for (int i = tid; i < BM * BN; i += 256) {
        const int r = i >> 7, c = i & 127;
        const float fv = Cs[i] + (bias ? bias[n0 + c] : 0.0f);
        if (bf16out) {
            __nv_bfloat16 h, l; bsplit(fv, h, l);
            Ch[(size_t)(m0 + r) * ldc + n0 + c] = h;
            Cl[(size_t)(m0 + r) * ldc + n0 + c] = l;
        } else {
            Cf[(size_t)(m0 + r) * ldc + n0 + c] = fv;
        }
    }
}

__global__ void __launch_bounds__(256) k_wgemm_f32(
    const __nv_bfloat16* Ah, const __nv_bfloat16* Al,
    const __nv_bfloat16* Bh, const __nv_bfloat16* Bl,
    const float* bias, float* Cf, int K, int ldc)
{
    wgemm_core(Ah, Al, Bh, Bl, bias, Cf, nullptr, nullptr, K, ldc, false);
}

__global__ void __launch_bounds__(256) k_wgemm_bf16(
    const __nv_bfloat16* Ah, const __nv_bfloat16* Al,
    const __nv_bfloat16* Bh, const __nv_bfloat16* Bl,
    const float* bias, __nv_bfloat16* Ch, __nv_bfloat16* Cl, int K, int ldc)
{
    wgemm_core(Ah, Al, Bh, Bl, bias, nullptr, Ch, Cl, K, ldc, true);
}

// ctx GEMM and Q GEMM fused into one launch (independent, selected by blockIdx.z)
__global__ void __launch_bounds__(256) k_wgemm_dual(
    const __nv_bfloat16* Ah0, const __nv_bfloat16* Al0,
    const __nv_bfloat16* Bh0, const __nv_bfloat16* Bl0,
    const float* b0, __nv_bfloat16* Ch0, __nv_bfloat16* Cl0, int ldc0,
    const __nv_bfloat16* Ah1, const __nv_bfloat16* Al1,
    const __nv_bfloat16* Bh1, const __nv_bfloat16* Bl1,
    const float* b1, __nv_bfloat16* Ch1, __nv_bfloat16* Cl1, int ldc1)
{
    if (blockIdx.z == 0)
        wgemm_core(Ah0, Al0, Bh0, Bl0, b0, nullptr, Ch0, Cl0, 256, ldc0, true);
    else
        wgemm_core(Ah1, Al1, Bh1, Bl1, b1, nullptr, Ch1, Cl1, 256, ldc1, true);
}

// ======================= attention (register-resident X) =====================
__global__ void __launch_bounds__(256) k_attn(const int* __restrict__ neigh,
                                              const float* __restrict__ feat)
{
    const int b = blockIdx.x;
    const int tid = threadIdx.x, wid = tid >> 5, lane = tid & 31;

    __shared__ int   idx[S_];
    __shared__ float sc[S_];
    __shared__ float part[8][256];

    if (tid < S_) idx[tid] = neigh[b * S_ + tid];

    // t for this row: lane holds cols [lane*8, lane*8+8)
    const float4 t0 = *(const float4*)&SC_t[b * F_ + lane * 8];
    const float4 t1 = *(const float4*)&SC_t[b * F_ + lane * 8 + 4];
    __syncthreads();

    // warp w owns rows 4w..4w+3, keeps X in registers
    float4 x0[4], x1[4];
#pragma unroll
    for (int r = 0; r < 4; r++) {
        const int s = wid * 4 + r;
        const float* row = feat + (size_t)idx[s] * F_ + lane * 8;
        x0[r] = *(const float4*)row;
        x1[r] = *(const float4*)(row + 4);
        float p = x0[r].x * t0.x + x0[r].y * t0.y + x0[r].z * t0.z + x0[r].w * t0.w
                + x1[r].x * t1.x + x1[r].y * t1.y + x1[r].z * t1.z + x1[r].w * t1.w;
#pragma unroll
        for (int o = 16; o; o >>= 1) p += __shfl_xor_sync(0xffffffffu, p, o);
        if (lane == 0) sc[s] = p;
    }
    __syncthreads();

    // softmax over the 32 neighbor scores (self slot masked by construction)
    if (tid < 32) {
        const float v = sc[tid];
        float mx = v;
#pragma unroll
        for (int o = 16; o; o >>= 1) mx = fmaxf(mx, __shfl_xor_sync(0xffffffffu, mx, o));
        const float e = expf(v - mx);
        float sum = e;
#pragma unroll
        for (int o = 16; o; o >>= 1) sum += __shfl_xor_sync(0xffffffffu, sum, o);
        sc[tid] = e / sum;
    }
    __syncthreads();

    // per-warp weighted partial sums, then cross-warp reduce
    float a0 = sc[wid * 4 + 0], a1 = sc[wid * 4 + 1],
          a2 = sc[wid * 4 + 2], a3 = sc[wid * 4 + 3];
    float4 acc0, acc1;
    acc0.x = a0 * x0[0].x + a1 * x0[1].x + a2 * x0[2].x + a3 * x0[3].x;
    acc0.y = a0 * x0[0].y + a1 * x0[1].y + a2 * x0[2].y + a3 * x0[3].y;
    acc0.z = a0 * x0[0].z + a1 * x0[1].z + a2 * x0[2].z + a3 * x0[3].z;
    acc0.w = a0 * x0[0].w + a1 * x0[1].w + a2 * x0[2].w + a3 * x0[3].w;
    acc1.x = a0 * x1[0].x + a1 * x1[1].x + a2 * x1[2].x + a3 * x1[3].x;
    acc1.y = a0 * x1[0].y + a1 * x1[1].y + a2 * x1[2].y + a3 * x1[3].y;
    acc1.z = a0 * x1[0].z + a1 * x1[1].z + a2 * x1[2].z + a3 * x1[3].z;
    acc1.w = a0 * x1[0].w + a1 * x1[1].w + a2 * x1[2].w + a3 * x1[3].w;
    *(float4*)&part[wid][lane * 8]     = acc0;
    *(float4*)&part[wid][lane * 8 + 4] = acc1;
    __syncthreads();

    float y = 0.f;
#pragma unroll
    for (int w = 0; w < 8; w++) y += part[w][tid];
    bsplit(y, G_Yh[b * F_ + tid], G_Yl[b * F_ + tid]);
}

// ======================= tanh + L2 normalize ================================
__global__ void __launch_bounds__(256) k_norm(float* __restrict__ out)
{
    const int b = blockIdx.x, tid = threadIdx.x;
    const float v = tanhf(SC_P[b * E_ + tid]);
    float ss = v * v;
    const int lane = tid & 31, wid = tid >> 5;
#pragma unroll
    for (int o = 16; o; o >>= 1) ss += __shfl_xor_sync(0xffffffffu, ss, o);
    __shared__ float red[8];
    if (lane == 0) red[wid] = ss;
    __syncthreads();
    float tot = 0.f;
#pragma unroll
    for (int i = 0; i < 8; i++) tot += red[i];
    const float scale = 1.0f / fmaxf(sqrtf(tot), 1e-12f);
    out[b * E_ + tid] = v * scale;
}

// ======================= host ===============================================
extern "C" void kernel_launch(void* const* d_in, const int* in_sizes, int n_in,
                              void* d_out, int out_size)
{
    const int*   nodes  = (const int*)  d_in[0];
    const int*   n_mean = (const int*)  d_in[1];
    const int*   n_attn = (const int*)  d_in[2];
    const float* feat   = (const float*)d_in[3];
    const float* Wm = (const float*)d_in[4],  *bm = (const float*)d_in[5];
    const float* Wq = (const float*)d_in[6],  *bq = (const float*)d_in[7];
    const float* Wk = (const float*)d_in[8];  // bk (d_in[9]) cancels in softmax
    const float* Wv = (const float*)d_in[10], *bv = (const float*)d_in[11];
    const float* Wc = (const float*)d_in[12], *bc = (const float*)d_in[13];
    float* out = (float*)d_out;

    __nv_bfloat16 *mh, *ml, *sh, *sl, *Qh, *Ql, *Yh, *Yl, *Zh, *Zl;
    __nv_bfloat16 *WmTh, *WmTl, *WqTh, *WqTl, *WvTh, *WvTl, *WcTh, *WcTl, *Wkh, *Wkl;
    float *pt, *pP;
    cudaGetSymbolAddress((void**)&mh, G_mh);   cudaGetSymbolAddress((void**)&ml, G_ml);
    cudaGetSymbolAddress((void**)&sh, G_sh);   cudaGetSymbolAddress((void**)&sl, G_sl);
    cudaGetSymbolAddress((void**)&Qh, G_Qh);   cudaGetSymbolAddress((void**)&Ql, G_Ql);
    cudaGetSymbolAddress((void**)&Yh, G_Yh);   cudaGetSymbolAddress((void**)&Yl, G_Yl);
    cudaGetSymbolAddress((void**)&Zh, G_Zh);   cudaGetSymbolAddress((void**)&Zl, G_Zl);
    cudaGetSymbolAddress((void**)&WmTh, G_WmTh); cudaGetSymbolAddress((void**)&WmTl, G_WmTl);
    cudaGetSymbolAddress((void**)&WqTh, G_WqTh); cudaGetSymbolAddress((void**)&WqTl, G_WqTl);
    cudaGetSymbolAddress((void**)&WvTh, G_WvTh); cudaGetSymbolAddress((void**)&WvTl, G_WvTl);
    cudaGetSymbolAddress((void**)&WcTh, G_WcTh); cudaGetSymbolAddress((void**)&WcTl, G_WcTl);
    cudaGetSymbolAddress((void**)&Wkh, G_Wkh); cudaGetSymbolAddress((void**)&Wkl, G_Wkl);
    cudaGetSymbolAddress((void**)&pt, SC_t);   cudaGetSymbolAddress((void**)&pP, SC_P);

    const dim3 ggrid(E_ / BN, B_ / BM, 1);       // (2, 64)
    const dim3 ggrid2(E_ / BN, B_ / BM, 2);      // dual

    // 1) weight prep (transpose + hi/lo split)
    k_prep<<<dim3(16, 8, 5), 256>>>(Wm, Wq, Wv, Wc, Wk);

    // 2) gathers: self feats + mean-aggregator mean (bf16 hi/lo out)
    k_gather<<<B_, 256>>>(nodes, n_mean, feat);

    // 3) ctx = m @ Wm + bm -> Z[:,256:512];  Q = self @ Wq + bq
    k_wgemm_dual<<<ggrid2, 256>>>(
        mh, ml, WmTh, WmTl, bm, Zh + E_, Zl + E_, 2 * E_,
        sh, sl, WqTh, WqTl, bq, Qh, Ql, E_);

    // 4) t = Q @ Wk^T (Wk as stored is [F][E] K-major; bk cancels)
    k_wgemm_f32<<<ggrid, 256>>>(Qh, Ql, Wkh, Wkl, nullptr, pt, E_, F_);

    // 5) attention -> y (bf16 hi/lo)
    k_attn<<<B_, 256>>>(n_attn, feat);

    // 6) mix = y @ Wv + bv -> Z[:,0:256]
    k_wgemm_bf16<<<ggrid, 256>>>(Yh, Yl, WvTh, WvTl, bv, Zh, Zl, F_, 2 * E_);

    // 7) P = Z @ Wc + bc  (K = 512)
    k_wgemm_f32<<<ggrid, 256>>>(Zh, Zl, WcTh, WcTl, bc, pP, 2 * E_, E_);

    // 8) out = L2-normalize(tanh(P))
    k_norm<<<B_, 256>>>(out);
}

// round 7
// speedup vs baseline: 1.3037x; 1.1174x over previous
#include <cuda_runtime.h>
#include <cuda_bf16.h>
#include <mma.h>
#include <cstdint>
#include <math.h>

using namespace nvcuda;

#define B_ 4096
#define S_ 32
#define F_ 256
#define E_ 256

#define BMT 64
#define BNT 64
#define SPAD 40          // bf16 elements per smem row (32 data + 8 pad)
#define BUFB (64 * SPAD) // elements per tile buffer

// ======================= scratch (__device__ globals) =======================
__device__ float SC_m   [B_ * F_];        // mean neighbor feats (f32)
__device__ float SC_self[B_ * F_];        // self feats (f32)
__device__ float SC_t   [B_ * F_];        // t = M @ self (raw, c added in attn)
__device__ float SC_y   [B_ * F_];        // attn-weighted feats
__device__ float SC_Z   [B_ * 2 * E_];    // [mix | ctx] f32
__device__ float SC_P   [B_ * E_];        // final pre-activation (raw)

// weights: [N][K] K-major, hi/lo bf16 split
__device__ __nv_bfloat16 G_WmTh[E_ * F_],     G_WmTl[E_ * F_];
__device__ __nv_bfloat16 G_WvTh[E_ * F_],     G_WvTl[E_ * F_];
__device__ __nv_bfloat16 G_WcTh[E_ * 2 * E_], G_WcTl[E_ * 2 * E_];
__device__ __nv_bfloat16 G_Mh[F_ * F_],       G_Ml[F_ * F_];   // M = Wk Wq^T
__device__ float G_c[F_];     // c = Wk bq
__device__ float G_pb[E_];    // pbias = [bv|bm]@Wc + bc

__device__ __forceinline__ void bsplit(float x, __nv_bfloat16& h, __nv_bfloat16& l) {
    h = __float2bfloat16(x);
    l = __float2bfloat16(x - __bfloat162float(h));
}

// split two floats -> packed (h1:h0) and (l1:l0) uint32 (no address-of locals)
__device__ __forceinline__ void split2pack(float x0, float x1, uint32_t& ph, uint32_t& pl) {
    __nv_bfloat16 h0, l0, h1, l1;
    bsplit(x0, h0, l0);
    bsplit(x1, h1, l1);
    ph = (uint32_t)__bfloat16_as_ushort(h0) | ((uint32_t)__bfloat16_as_ushort(h1) << 16);
    pl = (uint32_t)__bfloat16_as_ushort(l0) | ((uint32_t)__bfloat16_as_ushort(l1) << 16);
}

__device__ __forceinline__ uint32_t smem_u32(const void* p) {
    uint32_t a;
    asm("{ .reg .u64 t; cvta.to.shared.u64 t, %1; cvt.u32.u64 %0, t; }" : "=r"(a) : "l"(p));
    return a;
}
__device__ __forceinline__ void cp16(uint32_t dst, const void* src) {
    asm volatile("cp.async.ca.shared.global [%0], [%1], 16;" :: "r"(dst), "l"(src) : "memory");
}
__device__ __forceinline__ void cp_commit() { asm volatile("cp.async.commit_group;" ::: "memory"); }
__device__ __forceinline__ void cp_wait0()  { asm volatile("cp.async.wait_group 0;" ::: "memory"); }

// ======================= prep: weights, M, c, pbias =========================
__global__ void __launch_bounds__(256) k_prep(const float* __restrict__ Wm,
                                              const float* __restrict__ Wv,
                                              const float* __restrict__ Wc,
                                              const float* __restrict__ Wk,
                                              const float* __restrict__ Wq,
                                              const float* __restrict__ bq,
                                              const float* __restrict__ bv,
                                              const float* __restrict__ bm,
                                              const float* __restrict__ bc)
{
    const int z = blockIdx.z;
    if (z <= 2) {
        // transpose + hi/lo split:  W[K][256] -> WT[256][K]
        const float* W; __nv_bfloat16 *Oh, *Ol; int K;
        if      (z == 0) { W = Wm; Oh = G_WmTh; Ol = G_WmTl; K = 256; }
        else if (z == 1) { W = Wv; Oh = G_WvTh; Ol = G_WvTl; K = 256; }
        else             { W = Wc; Oh = G_WcTh; Ol = G_WcTl; K = 512; }
        const int k0 = blockIdx.x * 32, n0 = blockIdx.y * 32;
        if (k0 >= K) return;
        const int tx = threadIdx.x & 31, ty = threadIdx.x >> 5;
        __shared__ float tile[32][33];
#pragma unroll
        for (int i = 0; i < 4; i++)
            tile[ty + 8 * i][tx] = W[(size_t)(k0 + ty + 8 * i) * 256 + n0 + tx];
        __syncthreads();
#pragma unroll
        for (int i = 0; i < 4; i++) {
            const int n = n0 + ty + 8 * i, k = k0 + tx;
            bsplit(tile[tx][ty + 8 * i], Oh[(size_t)n * K + k], Ol[(size_t)n * K + k]);
        }
        return;
    }
    if (z == 3) {
        // M[f][x] = sum_e Wk[f,e] * Wq[x,e]; 32x32 tile per block (x<8, y<8)
        if (blockIdx.x >= 8) return;
        const int f0 = blockIdx.x * 32, x0 = blockIdx.y * 32;
        __shared__ float tK[32][33], tQ[32][33];
        const int r = threadIdx.x >> 5, cc = threadIdx.x & 31;
        float acc[4] = {0.f, 0.f, 0.f, 0.f};
        for (int e0 = 0; e0 < 256; e0 += 32) {
#pragma unroll
            for (int i = 0; i < 4; i++) {
                tK[r + 8 * i][cc] = Wk[(size_t)(f0 + r + 8 * i) * 256 + e0 + cc];
                tQ[r + 8 * i][cc] = Wq[(size_t)(x0 + r + 8 * i) * 256 + e0 + cc];
            }
            __syncthreads();
#pragma unroll
            for (int j = 0; j < 4; j++) {
                const int fl = r + 8 * j;
                float s = 0.f;
#pragma unroll
                for (int ee = 0; ee < 32; ee++)
                    s += tK[fl][ee] * tQ[cc][ee];
                acc[j] += s;
            }
            __syncthreads();
        }
#pragma unroll
        for (int j = 0; j < 4; j++)
            bsplit(acc[j], G_Mh[(size_t)(f0 + r + 8 * j) * 256 + x0 + cc],
                           G_Ml[(size_t)(f0 + r + 8 * j) * 256 + x0 + cc]);
        return;
    }
    // z == 4: vectors
    if (blockIdx.x == 0) {
        // c[f] = Wk[f,:] . bq ; block y handles 32 f, each warp 4 f
        const int wid = threadIdx.x >> 5, lane = threadIdx.x & 31;
#pragma unroll
        for (int j = 0; j < 4; j++) {
            const int f = blockIdx.y * 32 + wid * 4 + j;
            float p = 0.f;
#pragma unroll
            for (int k = 0; k < 8; k++)
                p += Wk[(size_t)f * 256 + lane + 32 * k] * bq[lane + 32 * k];
#pragma unroll
            for (int o = 16; o; o >>= 1) p += __shfl_xor_sync(0xffffffffu, p, o);
            if (lane == 0) G_c[f] = p;
        }
    } else if (blockIdx.x == 1 && blockIdx.y == 0) {
        // pbias[j] = bc[j] + sum_i bv[i] Wc[i,j] + sum_i bm[i] Wc[256+i,j]
        const int j = threadIdx.x;
        float s = bc[j];
        for (int i = 0; i < 256; i++) s += bv[i] * Wc[(size_t)i * 256 + j];
        for (int i = 0; i < 256; i++) s += bm[i] * Wc[(size_t)(256 + i) * 256 + j];
        G_pb[j] = s;
    }
}

// ======================= gather: self feats + mean-neighbor mean =============
__global__ void __launch_bounds__(256) k_gather(const int* __restrict__ nodes,
                                                const int* __restrict__ neigh,
                                                const float* __restrict__ feat)
{
    const int b = blockIdx.x;
    const int f = threadIdx.x;

    __shared__ int idx[S_];
    if (f < S_) idx[f] = neigh[b * S_ + f];
    SC_self[b * F_ + f] = feat[(size_t)nodes[b] * F_ + f];
    __syncthreads();

    float acc = 0.f;
#pragma unroll
    for (int s = 0; s < S_; s++)
        acc += feat[(size_t)idx[s] * F_ + f];
    SC_m[b * F_ + f] = acc * (1.0f / S_);
}

// ======================= WMMA GEMM core (v2) ================================
// C[64x64 tile] = A[f32, M x K] @ B^T  (B = h+l bf16, stored [N][K] K-major)
// 256 thr, 8 warps 4(M)x2(N), warp tile 16x32; BK=32; cp.async B double-buffered,
// register-prefetched A; one __syncthreads per K-step; direct f32 wmma store.
__device__ __forceinline__ void gcore(const float* __restrict__ A,
                                      const __nv_bfloat16* __restrict__ Bh,
                                      const __nv_bfloat16* __restrict__ Bl,
                                      float* __restrict__ C,
                                      int K, int ldc, int m0, int n0)
{
    __shared__ __align__(16) __nv_bfloat16 sAh[2][BUFB], sAl[2][BUFB];
    __shared__ __align__(16) __nv_bfloat16 sBh[2][BUFB], sBl[2][BUFB];

    const int tid = threadIdx.x, wid = tid >> 5;
    const int wm = wid & 3, wn = wid >> 2;
    const int lr = tid >> 2, lc = (tid & 3) * 8;   // loader: 64 rows x 4 thr/row

    wmma::fragment<wmma::accumulator, 16, 16, 16, float> acc[2];
    wmma::fill_fragment(acc[0], 0.0f);
    wmma::fill_fragment(acc[1], 0.0f);

    const uint32_t soff = (uint32_t)(lr * SPAD + lc) * 2;   // bytes; lr*80+lc*2, 16B-aligned
    const uint32_t uBh0 = smem_u32(&sBh[0][0]) + soff;
    const uint32_t uBl0 = smem_u32(&sBl[0][0]) + soff;
    const size_t   bsrc = (size_t)(n0 + lr) * K + lc;
    const size_t   asrc = (size_t)(m0 + lr) * K + lc;

    // prologue: issue B(0) cp.async, prefetch A(0) into registers
    cp16(uBh0, Bh + bsrc);
    cp16(uBl0, Bl + bsrc);
    cp_commit();
    float4 a0 = *(const float4*)(A + asrc);
    float4 a1 = *(const float4*)(A + asrc + 4);

    const int n_iter = K >> 5;
    for (int ch = 0; ch < n_iter; ch++) {
        const int buf = ch & 1;
        // STS A (f32 -> hi/lo bf16, packed in registers, one 16B store each)
        {
            uint4 uh, ul;
            split2pack(a0.x, a0.y, uh.x, ul.x);
            split2pack(a0.z, a0.w, uh.y, ul.y);
            split2pack(a1.x, a1.y, uh.z, ul.z);
            split2pack(a1.z, a1.w, uh.w, ul.w);
            *(uint4*)&sAh[buf][lr * SPAD + lc] = uh;
            *(uint4*)&sAl[buf][lr * SPAD + lc] = ul;
        }
        cp_wait0();
        __syncthreads();
        if (ch + 1 < n_iter) {
            const int k0 = (ch + 1) << 5;
            a0 = *(const float4*)(A + asrc + k0);
            a1 = *(const float4*)(A + asrc + k0 + 4);
            const uint32_t bo = (uint32_t)(buf ^ 1) * (BUFB * 2);
            cp16(uBh0 + bo, Bh + bsrc + k0);
            cp16(uBl0 + bo, Bl + bsrc + k0);
            cp_commit();
        }
#pragma unroll
        for (int kf = 0; kf < 2; kf++) {
            wmma::fragment<wmma::matrix_a, 16, 16, 16, __nv_bfloat16, wmma::row_major> ah, al;
            wmma::fragment<wmma::matrix_b, 16, 16, 16, __nv_bfloat16, wmma::col_major> bh[2], bl[2];
            wmma::load_matrix_sync(ah, &sAh[buf][(wm * 16) * SPAD + kf * 16], SPAD);
            wmma::load_matrix_sync(al, &sAl[buf][(wm * 16) * SPAD + kf * 16], SPAD);
#pragma unroll
            for (int ni = 0; ni < 2; ni++) {
                wmma::load_matrix_sync(bh[ni], &sBh[buf][(wn * 32 + ni * 16) * SPAD + kf * 16], SPAD);
                wmma::load_matrix_sync(bl[ni], &sBl[buf][(wn * 32 + ni * 16) * SPAD + kf * 16], SPAD);
            }
#pragma unroll
            for (int ni = 0; ni < 2; ni++) {
                wmma::mma_sync(acc[ni], ah, bh[ni], acc[ni]);
                wmma::mma_sync(acc[ni], ah, bl[ni], acc[ni]);
                wmma::mma_sync(acc[ni], al, bh[ni], acc[ni]);
            }
        }
    }
#pragma unroll
    for (int ni = 0; ni < 2; ni++)
        wmma::store_matrix_sync(&C[(size_t)(m0 + wm * 16) * ldc + n0 + wn * 32 + ni * 16],
                                acc[ni], ldc, wmma::mem_row_major);
}

// dual: z=0 ctx = m @ WmT -> Z[:,256:512];  z=1 t = self @ M^T -> SC_t
__global__ void __launch_bounds__(256) k_dual()
{
    const int m0 = blockIdx.y * BMT, n0 = blockIdx.x * BNT;
    if (blockIdx.z == 0)
        gcore(SC_m, G_WmTh, G_WmTl, SC_Z + E_, 256, 2 * E_, m0, n0);
    else
        gcore(SC_self, G_Mh, G_Ml, SC_t, 256, F_, m0, n0);
}
// mix = y @ WvT -> Z[:,0:256]
__global__ void __launch_bounds__(256) k_mix()
{
    gcore(SC_y, G_WvTh, G_WvTl, SC_Z, 256, 2 * E_, blockIdx.y * BMT, blockIdx.x * BNT);
}
// P = Z @ WcT (K=512) -> SC_P
__global__ void __launch_bounds__(256) k_final()
{
    gcore(SC_Z, G_WcTh, G_WcTl, SC_P, 512, E_, blockIdx.y * BMT, blockIdx.x * BNT);
}

// ======================= attention (register-resident X) =====================
__global__ void __launch_bounds__(256) k_attn(const int* __restrict__ neigh,
                                              const float* __restrict__ feat)
{
    const int b = blockIdx.x;
    const int tid = threadIdx.x, wid = tid >> 5, lane = tid & 31;

    __shared__ int   idx[S_];
    __shared__ float sc[S_];
    __shared__ __align__(16) float part[8][256];

    if (tid < S_) idx[tid] = neigh[b * S_ + tid];

    // t (+c) for this row: lane holds cols [lane*8, lane*8+8)
    float4 t0 = *(const float4*)&SC_t[b * F_ + lane * 8];
    float4 t1 = *(const float4*)&SC_t[b * F_ + lane * 8 + 4];
    const float4 c0 = *(const float4*)&G_c[lane * 8];
    const float4 c1 = *(const float4*)&G_c[lane * 8 + 4];
    t0.x += c0.x; t0.y += c0.y; t0.z += c0.z; t0.w += c0.w;
    t1.x += c1.x; t1.y += c1.y; t1.z += c1.z; t1.w += c1.w;
    __syncthreads();

    // warp w owns neighbor rows 4w..4w+3, X stays in registers
    float4 x0[4], x1[4];
#pragma unroll
    for (int r = 0; r < 4; r++) {
        const int s = wid * 4 + r;
        const float* row = feat + (size_t)idx[s] * F_ + lane * 8;
        x0[r] = *(const float4*)row;
        x1[r] = *(const float4*)(row + 4);
        float p = x0[r].x * t0.x + x0[r].y * t0.y + x0[r].z * t0.z + x0[r].w * t0.w
                + x1[r].x * t1.x + x1[r].y * t1.y + x1[r].z * t1.z + x1[r].w * t1.w;
#pragma unroll
        for (int o = 16; o; o >>= 1) p += __shfl_xor_sync(0xffffffffu, p, o);
        if (lane == 0) sc[s] = p;
    }
    __syncthreads();

    // softmax over 32 neighbors (self slot masked out by construction)
    if (tid < 32) {
        const float v = sc[tid];
        float mx = v;
#pragma unroll
        for (int o = 16; o; o >>= 1) mx = fmaxf(mx, __shfl_xor_sync(0xffffffffu, mx, o));
        const float e = expf(v - mx);
        float sum = e;
#pragma unroll
        for (int o = 16; o; o >>= 1) sum += __shfl_xor_sync(0xffffffffu, sum, o);
        sc[tid] = e / sum;
    }
    __syncthreads();

    const float a0 = sc[wid * 4 + 0], a1 = sc[wid * 4 + 1],
                a2 = sc[wid * 4 + 2], a3 = sc[wid * 4 + 3];
    float4 s0, s1;
    s0.x = a0 * x0[0].x + a1 * x0[1].x + a2 * x0[2].x + a3 * x0[3].x;
    s0.y = a0 * x0[0].y + a1 * x0[1].y + a2 * x0[2].y + a3 * x0[3].y;
    s0.z = a0 * x0[0].z + a1 * x0[1].z + a2 * x0[2].z + a3 * x0[3].z;
    s0.w = a0 * x0[0].w + a1 * x0[1].w + a2 * x0[2].w + a3 * x0[3].w;
    s1.x = a0 * x1[0].x + a1 * x1[1].x + a2 * x1[2].x + a3 * x1[3].x;
    s1.y = a0 * x1[0].y + a1 * x1[1].y + a2 * x1[2].y + a3 * x1[3].y;
    s1.z = a0 * x1[0].z + a1 * x1[1].z + a2 * x1[2].z + a3 * x1[3].z;
    s1.w = a0 * x1[0].w + a1 * x1[1].w + a2 * x1[2].w + a3 * x1[3].w;
    *(float4*)&part[wid][lane * 8]     = s0;
    *(float4*)&part[wid][lane * 8 + 4] = s1;
    __syncthreads();

    float y = 0.f;
#pragma unroll
    for (int w = 0; w < 8; w++) y += part[w][tid];
    SC_y[b * F_ + tid] = y;
}

// ======================= tanh(P + pbias) + L2 normalize ======================
__global__ void __launch_bounds__(256) k_norm(float* __restrict__ out)
{
    const int b = blockIdx.x, tid = threadIdx.x;
    const float v = tanhf(SC_P[b * E_ + tid] + G_pb[tid]);
    float ss = v * v;
    const int lane = tid & 31, wid = tid >> 5;
#pragma unroll
    for (int o = 16; o; o >>= 1) ss += __shfl_xor_sync(0xffffffffu, ss, o);
    __shared__ float red[8];
    if (lane == 0) red[wid] = ss;
    __syncthreads();
    float tot = 0.f;
#pragma unroll
    for (int i = 0; i < 8; i++) tot += red[i];
    const float scale = 1.0f / fmaxf(sqrtf(tot), 1e-12f);
    out[b * E_ + tid] = v * scale;
}

// ======================= host ===============================================
extern "C" void kernel_launch(void* const* d_in, const int* in_sizes, int n_in,
                              void* d_out, int out_size)
{
    const int*   nodes  = (const int*)  d_in[0];
    const int*   n_mean = (const int*)  d_in[1];
    const int*   n_attn = (const int*)  d_in[2];
    const float* feat   = (const float*)d_in[3];
    const float* Wm = (const float*)d_in[4],  *bm = (const float*)d_in[5];
    const float* Wq = (const float*)d_in[6],  *bq = (const float*)d_in[7];
    const float* Wk = (const float*)d_in[8];  // bk cancels in softmax
    const float* Wv = (const float*)d_in[10], *bv = (const float*)d_in[11];
    const float* Wc = (const float*)d_in[12], *bc = (const float*)d_in[13];
    float* out = (float*)d_out;

    const dim3 ggrid(E_ / BNT, B_ / BMT, 1);   // (4, 64)
    const dim3 ggrid2(E_ / BNT, B_ / BMT, 2);  // dual

    // 1) prep: weight transposes+splits, M = Wk Wq^T, c = Wk bq, pbias
    k_prep<<<dim3(16, 8, 5), 256>>>(Wm, Wv, Wc, Wk, Wq, bq, bv, bm, bc);

    // 2) gather: self feats + mean of mean-neighbors (f32)
    k_gather<<<B_, 256>>>(nodes, n_mean, feat);

    // 3) ctx -> Z[:,256:512]; t = self @ M^T (one wave, 512 CTAs)
    k_dual<<<ggrid2, 256>>>();

    // 4) attention -> y (adds c to t)
    k_attn<<<B_, 256>>>(n_attn, feat);

    // 5) mix = y @ WvT -> Z[:,0:256]
    k_mix<<<ggrid, 256>>>();

    // 6) P = Z @ WcT (K=512)
    k_final<<<ggrid, 256>>>();

    // 7) out = L2-normalize(tanh(P + pbias))
    k_norm<<<B_, 256>>>(out);
}

// round 8
// speedup vs baseline: 1.5786x; 1.2109x over previous
#include <cuda_runtime.h>
#include <cuda_bf16.h>
#include <mma.h>
#include <cstdint>
#include <math.h>

using namespace nvcuda;

#define B_ 4096
#define S_ 32
#define F_ 256
#define E_ 256

#define BMT 64
#define BNT 64
#define SPAD 40          // bf16 elements per smem row (32 data + 8 pad)
#define BUFB (64 * SPAD) // elements per tile buffer

// ======================= scratch (__device__ globals) =======================
__device__ float SC_self[B_ * F_];        // self feats (f32)
__device__ float SC_t   [B_ * F_];        // t = M @ self (raw, c added in attn)
__device__ float SC_ym  [B_ * 2 * F_];    // [y | m] per row, K=512 for P GEMM
__device__ float SC_P   [B_ * E_];        // final pre-activation (raw)

// precomputed operators, [N][K] K-major, hi/lo bf16 split
__device__ __nv_bfloat16 G_Mh[F_ * F_],   G_Ml[F_ * F_];       // M = Wk Wq^T
__device__ __nv_bfloat16 G_Wpch[E_ * 2 * F_], G_Wpcl[E_ * 2 * F_];  // [Wv@Wc_top | Wm@Wc_bot]^T
__device__ float G_c[F_];     // c = Wk bq
__device__ float G_pb[E_];    // pbias = bv@Wc_top + bm@Wc_bot + bc

__device__ __forceinline__ void bsplit(float x, __nv_bfloat16& h, __nv_bfloat16& l) {
    h = __float2bfloat16(x);
    l = __float2bfloat16(x - __bfloat162float(h));
}

// split two floats -> packed (h1:h0) and (l1:l0) uint32 (no address-of locals)
__device__ __forceinline__ void split2pack(float x0, float x1, uint32_t& ph, uint32_t& pl) {
    __nv_bfloat16 h0, l0, h1, l1;
    bsplit(x0, h0, l0);
    bsplit(x1, h1, l1);
    ph = (uint32_t)__bfloat16_as_ushort(h0) | ((uint32_t)__bfloat16_as_ushort(h1) << 16);
    pl = (uint32_t)__bfloat16_as_ushort(l0) | ((uint32_t)__bfloat16_as_ushort(l1) << 16);
}

__device__ __forceinline__ uint32_t smem_u32(const void* p) {
    uint32_t a;
    asm("{ .reg .u64 t; cvta.to.shared.u64 t, %1; cvt.u32.u64 %0, t; }" : "=r"(a) : "l"(p));
    return a;
}
__device__ __forceinline__ void cp16(uint32_t dst, const void* src) {
    asm volatile("cp.async.ca.shared.global [%0], [%1], 16;" :: "r"(dst), "l"(src) : "memory");
}
__device__ __forceinline__ void cp_commit() { asm volatile("cp.async.commit_group;" ::: "memory"); }
__device__ __forceinline__ void cp_wait0()  { asm volatile("cp.async.wait_group 0;" ::: "memory"); }

// ======================= prep: M, Wpc, c, pbias =============================
__global__ void __launch_bounds__(256) k_prep(const float* __restrict__ Wm,
                                              const float* __restrict__ Wv,
                                              const float* __restrict__ Wc,
                                              const float* __restrict__ Wk,
                                              const float* __restrict__ Wq,
                                              const float* __restrict__ bq,
                                              const float* __restrict__ bv,
                                              const float* __restrict__ bm,
                                              const float* __restrict__ bc)
{
    const int z = blockIdx.z;
    const int r = threadIdx.x >> 5, cc = threadIdx.x & 31;

    if (z == 0) {
        // M[f][x] = sum_e Wk[f,e] * Wq[x,e]
        const int f0 = blockIdx.x * 32, x0 = blockIdx.y * 32;
        __shared__ float tK[32][33], tQ[32][33];
        float acc[4] = {0.f, 0.f, 0.f, 0.f};
        for (int e0 = 0; e0 < 256; e0 += 32) {
#pragma unroll
            for (int i = 0; i < 4; i++) {
                tK[r + 8 * i][cc] = Wk[(size_t)(f0 + r + 8 * i) * 256 + e0 + cc];
                tQ[r + 8 * i][cc] = Wq[(size_t)(x0 + r + 8 * i) * 256 + e0 + cc];
            }
            __syncthreads();
#pragma unroll
            for (int j = 0; j < 4; j++) {
                float s = 0.f;
#pragma unroll
                for (int ee = 0; ee < 32; ee++)
                    s += tK[r + 8 * j][ee] * tQ[cc][ee];
                acc[j] += s;
            }
            __syncthreads();
        }
#pragma unroll
        for (int j = 0; j < 4; j++)
            bsplit(acc[j], G_Mh[(size_t)(f0 + r + 8 * j) * 256 + x0 + cc],
                           G_Ml[(size_t)(f0 + r + 8 * j) * 256 + x0 + cc]);
        return;
    }
    if (z == 1 || z == 2) {
        // Wpc[n][k(+256)] = sum_e Wx[k,e] * Wc[e(+256),n]   (z=1: Wv/top, z=2: Wm/bot)
        const float* Wx = (z == 1) ? Wv : Wm;
        const int erow0 = (z == 1) ? 0 : 256;
        const int kout0 = (z == 1) ? 0 : 256;
        const int n0 = blockIdx.x * 32, k0 = blockIdx.y * 32;
        __shared__ float tV[32][33], tC[32][33];
        float acc[4] = {0.f, 0.f, 0.f, 0.f};
        for (int e0 = 0; e0 < 256; e0 += 32) {
#pragma unroll
            for (int i = 0; i < 4; i++) {
                tV[r + 8 * i][cc] = Wx[(size_t)(k0 + r + 8 * i) * 256 + e0 + cc];
                tC[r + 8 * i][cc] = Wc[(size_t)(erow0 + e0 + r + 8 * i) * 256 + n0 + cc];
            }
            __syncthreads();
#pragma unroll
            for (int j = 0; j < 4; j++) {
                float s = 0.f;
#pragma unroll
                for (int ee = 0; ee < 32; ee++)
                    s += tV[cc][ee] * tC[ee][r + 8 * j];
                acc[j] += s;
            }
            __syncthreads();
        }
#pragma unroll
        for (int j = 0; j < 4; j++)
            bsplit(acc[j], G_Wpch[(size_t)(n0 + r + 8 * j) * 512 + kout0 + k0 + cc],
                           G_Wpcl[(size_t)(n0 + r + 8 * j) * 512 + kout0 + k0 + cc]);
        return;
    }
    // z == 3: vectors
    if (blockIdx.x == 0) {
        // c[f] = Wk[f,:] . bq ; blockIdx.y covers 32 f, each warp 4 f
        const int wid = r, lane = cc;
#pragma unroll
        for (int j = 0; j < 4; j++) {
            const int f = blockIdx.y * 32 + wid * 4 + j;
            float p = 0.f;
#pragma unroll
            for (int k = 0; k < 8; k++)
                p += Wk[(size_t)f * 256 + lane + 32 * k] * bq[lane + 32 * k];
#pragma unroll
            for (int o = 16; o; o >>= 1) p += __shfl_xor_sync(0xffffffffu, p, o);
            if (lane == 0) G_c[f] = p;
        }
    } else if (blockIdx.x == 1 && blockIdx.y == 0) {
        // pbias[j] = bc[j] + sum_i bv[i] Wc[i,j] + sum_i bm[i] Wc[256+i,j]
        const int j = threadIdx.x;
        float s = bc[j];
        for (int i = 0; i < 256; i++) s += bv[i] * Wc[(size_t)i * 256 + j];
        for (int i = 0; i < 256; i++) s += bm[i] * Wc[(size_t)(256 + i) * 256 + j];
        G_pb[j] = s;
    }
}

// ======================= self-row gather ====================================
// 1024 blocks x 256 thr; block handles 4 rows; 64 threads per row (float4 each)
__global__ void __launch_bounds__(256) k_self(const int* __restrict__ nodes,
                                              const float* __restrict__ feat)
{
    const int b = blockIdx.x * 4 + (threadIdx.x >> 6);
    const int c4 = (threadIdx.x & 63) * 4;
    const int node = nodes[b];
    *(float4*)&SC_self[(size_t)b * F_ + c4] =
        *(const float4*)&feat[(size_t)node * F_ + c4];
}

// ======================= WMMA GEMM core =====================================
// C[64x64 tile] = A[f32, M x K] @ B^T  (B = h+l bf16, stored [N][K] K-major)
// 256 thr, 8 warps 4(M)x2(N), warp tile 16x32; BK=32; cp.async B double-buffered,
// register-prefetched A; one __syncthreads per K-step; direct f32 wmma store.
__device__ __forceinline__ void gcore(const float* __restrict__ A,
                                      const __nv_bfloat16* __restrict__ Bh,
                                      const __nv_bfloat16* __restrict__ Bl,
                                      float* __restrict__ C,
                                      int K, int ldc, int m0, int n0)
{
    __shared__ __align__(16) __nv_bfloat16 sAh[2][BUFB], sAl[2][BUFB];
    __shared__ __align__(16) __nv_bfloat16 sBh[2][BUFB], sBl[2][BUFB];

    const int tid = threadIdx.x, wid = tid >> 5;
    const int wm = wid & 3, wn = wid >> 2;
    const int lr = tid >> 2, lc = (tid & 3) * 8;   // loader: 64 rows x 4 thr/row

    wmma::fragment<wmma::accumulator, 16, 16, 16, float> acc[2];
    wmma::fill_fragment(acc[0], 0.0f);
    wmma::fill_fragment(acc[1], 0.0f);

    const uint32_t soff = (uint32_t)(lr * SPAD + lc) * 2;
    const uint32_t uBh0 = smem_u32(&sBh[0][0]) + soff;
    const uint32_t uBl0 = smem_u32(&sBl[0][0]) + soff;
    const size_t   bsrc = (size_t)(n0 + lr) * K + lc;
    const size_t   asrc = (size_t)(m0 + lr) * K + lc;

    cp16(uBh0, Bh + bsrc);
    cp16(uBl0, Bl + bsrc);
    cp_commit();
    float4 a0 = *(const float4*)(A + asrc);
    float4 a1 = *(const float4*)(A + asrc + 4);

    const int n_iter = K >> 5;
    for (int ch = 0; ch < n_iter; ch++) {
        const int buf = ch & 1;
        {
            uint4 uh, ul;
            split2pack(a0.x, a0.y, uh.x, ul.x);
            split2pack(a0.z, a0.w, uh.y, ul.y);
            split2pack(a1.x, a1.y, uh.z, ul.z);
            split2pack(a1.z, a1.w, uh.w, ul.w);
            *(uint4*)&sAh[buf][lr * SPAD + lc] = uh;
            *(uint4*)&sAl[buf][lr * SPAD + lc] = ul;
        }
        cp_wait0();
        __syncthreads();
        if (ch + 1 < n_iter) {
            const int k0 = (ch + 1) << 5;
            a0 = *(const float4*)(A + asrc + k0);
            a1 = *(const float4*)(A + asrc + k0 + 4);
            const uint32_t bo = (uint32_t)(buf ^ 1) * (BUFB * 2);
            cp16(uBh0 + bo, Bh + bsrc + k0);
            cp16(uBl0 + bo, Bl + bsrc + k0);
            cp_commit();
        }
#pragma unroll
        for (int kf = 0; kf < 2; kf++) {
            wmma::fragment<wmma::matrix_a, 16, 16, 16, __nv_bfloat16, wmma::row_major> ah, al;
            wmma::fragment<wmma::matrix_b, 16, 16, 16, __nv_bfloat16, wmma::col_major> bh[2], bl[2];
            wmma::load_matrix_sync(ah, &sAh[buf][(wm * 16) * SPAD + kf * 16], SPAD);
            wmma::load_matrix_sync(al, &sAl[buf][(wm * 16) * SPAD + kf * 16], SPAD);
#pragma unroll
            for (int ni = 0; ni < 2; ni++) {
                wmma::load_matrix_sync(bh[ni], &sBh[buf][(wn * 32 + ni * 16) * SPAD + kf * 16], SPAD);
                wmma::load_matrix_sync(bl[ni], &sBl[buf][(wn * 32 + ni * 16) * SPAD + kf * 16], SPAD);
            }
#pragma unroll
            for (int ni = 0; ni < 2; ni++) {
                wmma::mma_sync(acc[ni], ah, bh[ni], acc[ni]);
                wmma::mma_sync(acc[ni], ah, bl[ni], acc[ni]);
                wmma::mma_sync(acc[ni], al, bh[ni], acc[ni]);
            }
        }
    }
#pragma unroll
    for (int ni = 0; ni < 2; ni++)
        wmma::store_matrix_sync(&C[(size_t)(m0 + wm * 16) * ldc + n0 + wn * 32 + ni * 16],
                                acc[ni], ldc, wmma::mem_row_major);
}

// t = self @ M^T
__global__ void __launch_bounds__(256) k_tg()
{
    gcore(SC_self, G_Mh, G_Ml, SC_t, 256, F_, blockIdx.y * BMT, blockIdx.x * BNT);
}
// P = ym @ Wpc^T  (K = 512)
__global__ void __launch_bounds__(256) k_pg()
{
    gcore(SC_ym, G_Wpch, G_Wpcl, SC_P, 512, E_, blockIdx.y * BMT, blockIdx.x * BNT);
}

// ======================= fused attention + mean aggregation ==================
__global__ void __launch_bounds__(256) k_attn(const int* __restrict__ neigh_attn,
                                              const int* __restrict__ neigh_mean,
                                              const float* __restrict__ feat)
{
    const int b = blockIdx.x;
    const int tid = threadIdx.x, wid = tid >> 5, lane = tid & 31;

    __shared__ int   idxA[S_], idxM[S_];
    __shared__ float sc[S_];
    __shared__ __align__(16) float part[8][256];

    if (tid < S_)           idxA[tid]      = neigh_attn[b * S_ + tid];
    else if (tid < 2 * S_)  idxM[tid - S_] = neigh_mean[b * S_ + tid - S_];

    // t (+c) for this row: lane holds cols [lane*8, lane*8+8)
    float4 t0 = *(const float4*)&SC_t[b * F_ + lane * 8];
    float4 t1 = *(const float4*)&SC_t[b * F_ + lane * 8 + 4];
    const float4 c0 = *(const float4*)&G_c[lane * 8];
    const float4 c1 = *(const float4*)&G_c[lane * 8 + 4];
    t0.x += c0.x; t0.y += c0.y; t0.z += c0.z; t0.w += c0.w;
    t1.x += c1.x; t1.y += c1.y; t1.z += c1.z; t1.w += c1.w;
    __syncthreads();

    // warp w owns attn rows 4w..4w+3; batch all 8 LDG.128 before any shuffle
    float4 x0[4], x1[4];
#pragma unroll
    for (int r = 0; r < 4; r++) {
        const float* row = feat + (size_t)idxA[wid * 4 + r] * F_ + lane * 8;
        x0[r] = *(const float4*)row;
        x1[r] = *(const float4*)(row + 4);
    }
    float p[4];
#pragma unroll
    for (int r = 0; r < 4; r++)
        p[r] = x0[r].x * t0.x + x0[r].y * t0.y + x0[r].z * t0.z + x0[r].w * t0.w
             + x1[r].x * t1.x + x1[r].y * t1.y + x1[r].z * t1.z + x1[r].w * t1.w;
#pragma unroll
    for (int o = 16; o; o >>= 1)
#pragma unroll
        for (int r = 0; r < 4; r++)
            p[r] += __shfl_xor_sync(0xffffffffu, p[r], o);
    if (lane < 4) sc[wid * 4 + lane] = p[lane];   // lane r holds reduced p[r]
    __syncthreads();

    // softmax over 32 neighbor scores (self slot masked out by construction)
    if (tid < 32) {
        const float v = sc[tid];
        float mx = v;
#pragma unroll
        for (int o = 16; o; o >>= 1) mx = fmaxf(mx, __shfl_xor_sync(0xffffffffu, mx, o));
        const float e = expf(v - mx);
        float sum = e;
#pragma unroll
        for (int o = 16; o; o >>= 1) sum += __shfl_xor_sync(0xffffffffu, sum, o);
        sc[tid] = e / sum;
    }
    __syncthreads();

    const float a0 = sc[wid * 4 + 0], a1 = sc[wid * 4 + 1],
                a2 = sc[wid * 4 + 2], a3 = sc[wid * 4 + 3];
    float4 s0, s1;
    s0.x = a0 * x0[0].x + a1 * x0[1].x + a2 * x0[2].x + a3 * x0[3].x;
    s0.y = a0 * x0[0].y + a1 * x0[1].y + a2 * x0[2].y + a3 * x0[3].y;
    s0.z = a0 * x0[0].z + a1 * x0[1].z + a2 * x0[2].z + a3 * x0[3].z;
    s0.w = a0 * x0[0].w + a1 * x0[1].w + a2 * x0[2].w + a3 * x0[3].w;
    s1.x = a0 * x1[0].x + a1 * x1[1].x + a2 * x1[2].x + a3 * x1[3].x;
    s1.y = a0 * x1[0].y + a1 * x1[1].y + a2 * x1[2].y + a3 * x1[3].y;
    s1.z = a0 * x1[0].z + a1 * x1[1].z + a2 * x1[2].z + a3 * x1[3].z;
    s1.w = a0 * x1[0].w + a1 * x1[1].w + a2 * x1[2].w + a3 * x1[3].w;
    *(float4*)&part[wid][lane * 8]     = s0;
    *(float4*)&part[wid][lane * 8 + 4] = s1;
    __syncthreads();

    float y = 0.f;
#pragma unroll
    for (int w = 0; w < 8; w++) y += part[w][tid];
    SC_ym[(size_t)b * 512 + tid] = y;
    __syncthreads();   // part fully consumed before mean pass reuses it

    // mean aggregation over neigh_mean rows (reuse x regs + part buffer)
#pragma unroll
    for (int r = 0; r < 4; r++) {
        const float* row = feat + (size_t)idxM[wid * 4 + r] * F_ + lane * 8;
        x0[r] = *(const float4*)row;
        x1[r] = *(const float4*)(row + 4);
    }
    s0.x = x0[0].x + x0[1].x + x0[2].x + x0[3].x;
    s0.y = x0[0].y + x0[1].y + x0[2].y + x0[3].y;
    s0.z = x0[0].z + x0[1].z + x0[2].z + x0[3].z;
    s0.w = x0[0].w + x0[1].w + x0[2].w + x0[3].w;
    s1.x = x1[0].x + x1[1].x + x1[2].x + x1[3].x;
    s1.y = x1[0].y + x1[1].y + x1[2].y + x1[3].y;
    s1.z = x1[0].z + x1[1].z + x1[2].z + x1[3].z;
    s1.w = x1[0].w + x1[1].w + x1[2].w + x1[3].w;
    *(float4*)&part[wid][lane * 8]     = s0;
    *(float4*)&part[wid][lane * 8 + 4] = s1;
    __syncthreads();

    float m = 0.f;
#pragma unroll
    for (int w = 0; w < 8; w++) m += part[w][tid];
    SC_ym[(size_t)b * 512 + 256 + tid] = m * (1.0f / S_);
}

// ======================= tanh(P + pbias) + L2 normalize ======================
__global__ void __launch_bounds__(256) k_norm(float* __restrict__ out)
{
    const int b = blockIdx.x, tid = threadIdx.x;
    const float v = tanhf(SC_P[b * E_ + tid] + G_pb[tid]);
    float ss = v * v;
    const int lane = tid & 31, wid = tid >> 5;
#pragma unroll
    for (int o = 16; o; o >>= 1) ss += __shfl_xor_sync(0xffffffffu, ss, o);
    __shared__ float red[8];
    if (lane == 0) red[wid] = ss;
    __syncthreads();
    float tot = 0.f;
#pragma unroll
    for (int i = 0; i < 8; i++) tot += red[i];
    const float scale = 1.0f / fmaxf(sqrtf(tot), 1e-12f);
    out[b * E_ + tid] = v * scale;
}

// ======================= host ===============================================
extern "C" void kernel_launch(void* const* d_in, const int* in_sizes, int n_in,
                              void* d_out, int out_size)
{
    const int*   nodes  = (const int*)  d_in[0];
    const int*   n_mean = (const int*)  d_in[1];
    const int*   n_attn = (const int*)  d_in[2];
    const float* feat   = (const float*)d_in[3];
    const float* Wm = (const float*)d_in[4],  *bm = (const float*)d_in[5];
    const float* Wq = (const float*)d_in[6],  *bq = (const float*)d_in[7];
    const float* Wk = (const float*)d_in[8];  // bk cancels in softmax
    const float* Wv = (const float*)d_in[10], *bv = (const float*)d_in[11];
    const float* Wc = (const float*)d_in[12], *bc = (const float*)d_in[13];
    float* out = (float*)d_out;

    const dim3 ggrid(E_ / BNT, B_ / BMT, 1);   // (4, 64) = 256 CTAs

    // 1) prep: M = Wk Wq^T, Wpc = [Wv@Wc_top | Wm@Wc_bot]^T, c, pbias
    k_prep<<<dim3(8, 8, 4), 256>>>(Wm, Wv, Wc, Wk, Wq, bq, bv, bm, bc);

    // 2) gather self rows
    k_self<<<B_ / 4, 256>>>(nodes, feat);

    // 3) t = self @ M^T
    k_tg<<<ggrid, 256>>>();

    // 4) fused attention + mean aggregation -> ym = [y | m]
    k_attn<<<B_, 256>>>(n_attn, n_mean, feat);

    // 5) P = ym @ Wpc^T  (K = 512)
    k_pg<<<ggrid, 256>>>();

    // 6) out = L2-normalize(tanh(P + pbias))
    k_norm<<<B_, 256>>>(out);
}

// round 10
// speedup vs baseline: 1.8183x; 1.1518x over previous
#include <cuda_runtime.h>
#include <cuda_bf16.h>
#include <mma.h>
#include <cstdint>
#include <math.h>

using namespace nvcuda;

#define B_ 4096
#define S_ 32
#define F_ 256
#define E_ 256

#define BMT 64
#define BNT 64
#define SPAD 40          // bf16 elements per smem row (32 data + 8 pad)
#define BUFB (64 * SPAD) // elements per tile buffer

// ======================= scratch (__device__ globals) =======================
__device__ float SC_t   [B_ * F_];        // t = M @ self (raw, c added in attn)
__device__ float SC_ym  [B_ * 2 * F_];    // [y | m] per row, K=512 for P GEMM
__device__ float SC_P   [B_ * E_];        // final pre-activation (raw)

// precomputed operators, [N][K] K-major, hi/lo bf16 split
__device__ __nv_bfloat16 G_Mh[F_ * F_],   G_Ml[F_ * F_];       // M = Wk Wq^T
__device__ __nv_bfloat16 G_Wpch[E_ * 2 * F_], G_Wpcl[E_ * 2 * F_];  // [Wv@Wc_top | Wm@Wc_bot]^T
__device__ float G_c[F_];     // c = Wk bq
__device__ float G_pb[E_];    // pbias = bv@Wc_top + bm@Wc_bot + bc

__device__ __forceinline__ void bsplit(float x, __nv_bfloat16& h, __nv_bfloat16& l) {
    h = __float2bfloat16(x);
    l = __float2bfloat16(x - __bfloat162float(h));
}

// split two floats -> packed (h1:h0) and (l1:l0) uint32 (no address-of locals)
__device__ __forceinline__ void split2pack(float x0, float x1, uint32_t& ph, uint32_t& pl) {
    __nv_bfloat16 h0, l0, h1, l1;
    bsplit(x0, h0, l0);
    bsplit(x1, h1, l1);
    ph = (uint32_t)__bfloat16_as_ushort(h0) | ((uint32_t)__bfloat16_as_ushort(h1) << 16);
    pl = (uint32_t)__bfloat16_as_ushort(l0) | ((uint32_t)__bfloat16_as_ushort(l1) << 16);
}

__device__ __forceinline__ uint32_t smem_u32(const void* p) {
    uint32_t a;
    asm("{ .reg .u64 t; cvta.to.shared.u64 t, %1; cvt.u32.u64 %0, t; }" : "=r"(a) : "l"(p));
    return a;
}
__device__ __forceinline__ void cp16(uint32_t dst, const void* src) {
    asm volatile("cp.async.ca.shared.global [%0], [%1], 16;" :: "r"(dst), "l"(src) : "memory");
}
__device__ __forceinline__ void cp_commit() { asm volatile("cp.async.commit_group;" ::: "memory"); }
__device__ __forceinline__ void cp_wait0()  { asm volatile("cp.async.wait_group 0;" ::: "memory"); }

// ======================= prep: M, Wpc, c, pbias =============================
__global__ void __launch_bounds__(256) k_prep(const float* __restrict__ Wm,
                                              const float* __restrict__ Wv,
                                              const float* __restrict__ Wc,
                                              const float* __restrict__ Wk,
                                              const float* __restrict__ Wq,
                                              const float* __restrict__ bq,
                                              const float* __restrict__ bv,
                                              const float* __restrict__ bm,
                                              const float* __restrict__ bc)
{
    const int z = blockIdx.z;
    const int r = threadIdx.x >> 5, cc = threadIdx.x & 31;

    if (z == 0) {
        // M[f][x] = sum_e Wk[f,e] * Wq[x,e]
        const int f0 = blockIdx.x * 32, x0 = blockIdx.y * 32;
        __shared__ float tK[32][33], tQ[32][33];
        float acc[4] = {0.f, 0.f, 0.f, 0.f};
        for (int e0 = 0; e0 < 256; e0 += 32) {
#pragma unroll
            for (int i = 0; i < 4; i++) {
                tK[r + 8 * i][cc] = Wk[(size_t)(f0 + r + 8 * i) * 256 + e0 + cc];
                tQ[r + 8 * i][cc] = Wq[(size_t)(x0 + r + 8 * i) * 256 + e0 + cc];
            }
            __syncthreads();
#pragma unroll
            for (int j = 0; j < 4; j++) {
                float s = 0.f;
#pragma unroll
                for (int ee = 0; ee < 32; ee++)
                    s += tK[r + 8 * j][ee] * tQ[cc][ee];
                acc[j] += s;
            }
            __syncthreads();
        }
#pragma unroll
        for (int j = 0; j < 4; j++)
            bsplit(acc[j], G_Mh[(size_t)(f0 + r + 8 * j) * 256 + x0 + cc],
                           G_Ml[(size_t)(f0 + r + 8 * j) * 256 + x0 + cc]);
        return;
    }
    if (z == 1 || z == 2) {
        // Wpc[n][k(+256)] = sum_e Wx[k,e] * Wc[e(+256),n]   (z=1: Wv/top, z=2: Wm/bot)
        const float* Wx = (z == 1) ? Wv : Wm;
        const int erow0 = (z == 1) ? 0 : 256;
        const int kout0 = (z == 1) ? 0 : 256;
        const int n0 = blockIdx.x * 32, k0 = blockIdx.y * 32;
        __shared__ float tV[32][33], tC[32][33];
        float acc[4] = {0.f, 0.f, 0.f, 0.f};
        for (int e0 = 0; e0 < 256; e0 += 32) {
#pragma unroll
            for (int i = 0; i < 4; i++) {
                tV[r + 8 * i][cc] = Wx[(size_t)(k0 + r + 8 * i) * 256 + e0 + cc];
                tC[r + 8 * i][cc] = Wc[(size_t)(erow0 + e0 + r + 8 * i) * 256 + n0 + cc];
            }
            __syncthreads();
#pragma unroll
            for (int j = 0; j < 4; j++) {
                float s = 0.f;
#pragma unroll
                for (int ee = 0; ee < 32; ee++)
                    s += tV[cc][ee] * tC[ee][r + 8 * j];
                acc[j] += s;
            }
            __syncthreads();
        }
#pragma unroll
        for (int j = 0; j < 4; j++)
            bsplit(acc[j], G_Wpch[(size_t)(n0 + r + 8 * j) * 512 + kout0 + k0 + cc],
                           G_Wpcl[(size_t)(n0 + r + 8 * j) * 512 + kout0 + k0 + cc]);
        return;
    }
    // z == 3: vectors
    if (blockIdx.x == 0) {
        // c[f] = Wk[f,:] . bq ; blockIdx.y covers 32 f, each warp 4 f
        const int wid = r, lane = cc;
#pragma unroll
        for (int j = 0; j < 4; j++) {
            const int f = blockIdx.y * 32 + wid * 4 + j;
            float p = 0.f;
#pragma unroll
            for (int k = 0; k < 8; k++)
                p += Wk[(size_t)f * 256 + lane + 32 * k] * bq[lane + 32 * k];
#pragma unroll
            for (int o = 16; o; o >>= 1) p += __shfl_xor_sync(0xffffffffu, p, o);
            if (lane == 0) G_c[f] = p;
        }
    } else if (blockIdx.x == 1 && blockIdx.y == 0) {
        // pbias[j] = bc[j] + sum_i bv[i] Wc[i,j] + sum_i bm[i] Wc[256+i,j]
        const int j = threadIdx.x;
        float s = bc[j];
        for (int i = 0; i < 256; i++) s += bv[i] * Wc[(size_t)i * 256 + j];
        for (int i = 0; i < 256; i++) s += bm[i] * Wc[(size_t)(256 + i) * 256 + j];
        G_pb[j] = s;
    }
}

// ======================= WMMA GEMM core =====================================
// C[64x64 tile] = A[f32, M x K] @ B^T  (B = h+l bf16, stored [N][K] K-major)
// GATHER: A row i is feat[ridx[m0+i]] (fuses the self-row gather into the GEMM).
// 256 thr, 8 warps 4(M)x2(N), warp tile 16x32; BK=32; cp.async B double-buffered,
// register-prefetched A; one __syncthreads per K-step; direct f32 wmma store.
template <bool GATHER>
__device__ __forceinline__ void gcore(const float* __restrict__ A,
                                      const int* __restrict__ ridx,
                                      const __nv_bfloat16* __restrict__ Bh,
                                      const __nv_bfloat16* __restrict__ Bl,
                                      float* __restrict__ C,
                                      int K, int ldc, int m0, int n0)
{
    __shared__ __align__(16) __nv_bfloat16 sAh[2][BUFB], sAl[2][BUFB];
    __shared__ __align__(16) __nv_bfloat16 sBh[2][BUFB], sBl[2][BUFB];

    const int tid = threadIdx.x, wid = tid >> 5;
    const int wm = wid & 3, wn = wid >> 2;
    const int lr = tid >> 2, lc = (tid & 3) * 8;   // loader: 64 rows x 4 thr/row

    wmma::fragment<wmma::accumulator, 16, 16, 16, float> acc[2];
    wmma::fill_fragment(acc[0], 0.0f);
    wmma::fill_fragment(acc[1], 0.0f);

    const uint32_t soff = (uint32_t)(lr * SPAD + lc) * 2;
    const uint32_t uBh0 = smem_u32(&sBh[0][0]) + soff;
    const uint32_t uBl0 = smem_u32(&sBl[0][0]) + soff;
    const size_t   bsrc = (size_t)(n0 + lr) * K + lc;
    const size_t   arow = GATHER ? (size_t)ridx[m0 + lr] * K : (size_t)(m0 + lr) * K;
    const size_t   asrc = arow + lc;

    cp16(uBh0, Bh + bsrc);
    cp16(uBl0, Bl + bsrc);
    cp_commit();
    float4 a0 = *(const float4*)(A + asrc);
    float4 a1 = *(const float4*)(A + asrc + 4);

    const int n_iter = K >> 5;
    for (int ch = 0; ch < n_iter; ch++) {
        const int buf = ch & 1;
        {
            uint4 uh, ul;
            split2pack(a0.x, a0.y, uh.x, ul.x);
            split2pack(a0.z, a0.w, uh.y, ul.y);
            split2pack(a1.x, a1.y, uh.z, ul.z);
            split2pack(a1.z, a1.w, uh.w, ul.w);
            *(uint4*)&sAh[buf][lr * SPAD + lc] = uh;
            *(uint4*)&sAl[buf][lr * SPAD + lc] = ul;
        }
        cp_wait0();
        __syncthreads();
        if (ch + 1 < n_iter) {
            const int k0 = (ch + 1) << 5;
            a0 = *(const float4*)(A + asrc + k0);
            a1 = *(const float4*)(A + asrc + k0 + 4);
            const uint32_t bo = (uint32_t)(buf ^ 1) * (BUFB * 2);
            cp16(uBh0 + bo, Bh + bsrc + k0);
            cp16(uBl0 + bo, Bl + bsrc + k0);
            cp_commit();
        }
#pragma unroll
        for (int kf = 0; kf < 2; kf++) {
            wmma::fragment<wmma::matrix_a, 16, 16, 16, __nv_bfloat16, wmma::row_major> ah, al;
            wmma::fragment<wmma::matrix_b, 16, 16, 16, __nv_bfloat16, wmma::col_major> bh[2], bl[2];
            wmma::load_matrix_sync(ah, &sAh[buf][(wm * 16) * SPAD + kf * 16], SPAD);
            wmma::load_matrix_sync(al, &sAl[buf][(wm * 16) * SPAD + kf * 16], SPAD);
#pragma unroll
            for (int ni = 0; ni < 2; ni++) {
                wmma::load_matrix_sync(bh[ni], &sBh[buf][(wn * 32 + ni * 16) * SPAD + kf * 16], SPAD);
                wmma::load_matrix_sync(bl[ni], &sBl[buf][(wn * 32 + ni * 16) * SPAD + kf * 16], SPAD);
            }
#pragma unroll
            for (int ni = 0; ni < 2; ni++) {
                wmma::mma_sync(acc[ni], ah, bh[ni], acc[ni]);
                wmma::mma_sync(acc[ni], ah, bl[ni], acc[ni]);
                wmma::mma_sync(acc[ni], al, bh[ni], acc[ni]);
            }
        }
    }
#pragma unroll
    for (int ni = 0; ni < 2; ni++)
        wmma::store_matrix_sync(&C[(size_t)(m0 + wm * 16) * ldc + n0 + wn * 32 + ni * 16],
                                acc[ni], ldc, wmma::mem_row_major);
}

// t = feat[nodes] @ M^T  (self-gather fused into the A loader)
__global__ void __launch_bounds__(256) k_tg(const int* __restrict__ nodes,
                                            const float* __restrict__ feat)
{
    gcore<true>(feat, nodes, G_Mh, G_Ml, SC_t, 256, F_, blockIdx.y * BMT, blockIdx.x * BNT);
}
// P = ym @ Wpc^T  (K = 512)
__global__ void __launch_bounds__(256) k_pg()
{
    gcore<false>(SC_ym, nullptr, G_Wpch, G_Wpcl, SC_P, 512, E_, blockIdx.y * BMT, blockIdx.x * BNT);
}

// ======================= fused attention + mean aggregation ==================
// Coalesced mapping: lane l covers cols {4l..4l+3} (chunk0) and {128+4l..} (chunk1)
__global__ void __launch_bounds__(256) k_attn(const int* __restrict__ neigh_attn,
                                              const int* __restrict__ neigh_mean,
                                              const float* __restrict__ feat)
{
    const int b = blockIdx.x;
    const int tid = threadIdx.x, wid = tid >> 5, lane = tid & 31;

    __shared__ int   idxA[S_], idxM[S_];
    __shared__ float sc[S_];
    __shared__ __align__(16) float part[8][256];

    if (tid < S_)           idxA[tid]      = neigh_attn[b * S_ + tid];
    else if (tid < 2 * S_)  idxM[tid - S_] = neigh_mean[b * S_ + tid - S_];

    // t (+c): lane holds cols [4l,4l+4) and [128+4l, 128+4l+4)
    float4 t0 = *(const float4*)&SC_t[b * F_ + lane * 4];
    float4 t1 = *(const float4*)&SC_t[b * F_ + 128 + lane * 4];
    const float4 c0 = *(const float4*)&G_c[lane * 4];
    const float4 c1 = *(const float4*)&G_c[128 + lane * 4];
    t0.x += c0.x; t0.y += c0.y; t0.z += c0.z; t0.w += c0.w;
    t1.x += c1.x; t1.y += c1.y; t1.z += c1.z; t1.w += c1.w;
    __syncthreads();

    // warp w owns attn rows 4w..4w+3; fully-coalesced LDG.128 (512B contiguous)
    float4 x0[4], x1[4];
#pragma unroll
    for (int r = 0; r < 4; r++) {
        const float* row = feat + (size_t)idxA[wid * 4 + r] * F_;
        x0[r] = *(const float4*)(row + lane * 4);
        x1[r] = *(const float4*)(row + 128 + lane * 4);
    }
    float p[4];
#pragma unroll
    for (int r = 0; r < 4; r++)
        p[r] = x0[r].x * t0.x + x0[r].y * t0.y + x0[r].z * t0.z + x0[r].w * t0.w
             + x1[r].x * t1.x + x1[r].y * t1.y + x1[r].z * t1.z + x1[r].w * t1.w;
#pragma unroll
    for (int o = 16; o; o >>= 1)
#pragma unroll
        for (int r = 0; r < 4; r++)
            p[r] += __shfl_xor_sync(0xffffffffu, p[r], o);
    if (lane == 0) {
        sc[wid * 4 + 0] = p[0];
        sc[wid * 4 + 1] = p[1];
        sc[wid * 4 + 2] = p[2];
        sc[wid * 4 + 3] = p[3];
    }
    __syncthreads();

    // softmax over 32 neighbor scores (self slot masked out by construction)
    if (tid < 32) {
        const float v = sc[tid];
        float mx = v;
#pragma unroll
        for (int o = 16; o; o >>= 1) mx = fmaxf(mx, __shfl_xor_sync(0xffffffffu, mx, o));
        const float e = __expf(v - mx);
        float sum = e;
#pragma unroll
        for (int o = 16; o; o >>= 1) sum += __shfl_xor_sync(0xffffffffu, sum, o);
        sc[tid] = e / sum;
    }
    __syncthreads();

    const float a0 = sc[wid * 4 + 0], a1 = sc[wid * 4 + 1],
                a2 = sc[wid * 4 + 2], a3 = sc[wid * 4 + 3];
    float4 s0, s1;
    s0.x = a0 * x0[0].x + a1 * x0[1].x + a2 * x0[2].x + a3 * x0[3].x;
    s0.y = a0 * x0[0].y + a1 * x0[1].y + a2 * x0[2].y + a3 * x0[3].y;
    s0.z = a0 * x0[0].z + a1 * x0[1].z + a2 * x0[2].z + a3 * x0[3].z;
    s0.w = a0 * x0[0].w + a1 * x0[1].w + a2 * x0[2].w + a3 * x0[3].w;
    s1.x = a0 * x1[0].x + a1 * x1[1].x + a2 * x1[2].x + a3 * x1[3].x;
    s1.y = a0 * x1[0].y + a1 * x1[1].y + a2 * x1[2].y + a3 * x1[3].y;
    s1.z = a0 * x1[0].z + a1 * x1[1].z + a2 * x1[2].z + a3 * x1[3].z;
    s1.w = a0 * x1[0].w + a1 * x1[1].w + a2 * x1[2].w + a3 * x1[3].w;
    *(float4*)&part[wid][lane * 4]       = s0;
    *(float4*)&part[wid][128 + lane * 4] = s1;
    __syncthreads();

    float y = 0.f;
#pragma unroll
    for (int w = 0; w < 8; w++) y += part[w][tid];
    SC_ym[(size_t)b * 512 + tid] = y;
    __syncthreads();   // part fully consumed before mean pass reuses it

    // mean aggregation over neigh_mean rows (reuse x regs + part buffer)
#pragma unroll
    for (int r = 0; r < 4; r++) {
        const float* row = feat + (size_t)idxM[wid * 4 + r] * F_;
        x0[r] = *(const float4*)(row + lane * 4);
        x1[r] = *(const float4*)(row + 128 + lane * 4);
    }
    s0.x = x0[0].x + x0[1].x + x0[2].x + x0[3].x;
    s0.y = x0[0].y + x0[1].y + x0[2].y + x0[3].y;
    s0.z = x0[0].z + x0[1].z + x0[2].z + x0[3].z;
    s0.w = x0[0].w + x0[1].w + x0[2].w + x0[3].w;
    s1.x = x1[0].x + x1[1].x + x1[2].x + x1[3].x;
    s1.y = x1[0].y + x1[1].y + x1[2].y + x1[3].y;
    s1.z = x1[0].z + x1[1].z + x1[2].z + x1[3].z;
    s1.w = x1[0].w + x1[1].w + x1[2].w + x1[3].w;
    *(float4*)&part[wid][lane * 4]       = s0;
    *(float4*)&part[wid][128 + lane * 4] = s1;
    __syncthreads();

    float m = 0.f;
#pragma unroll
    for (int w = 0; w < 8; w++) m += part[w][tid];
    SC_ym[(size_t)b * 512 + 256 + tid] = m * (1.0f / S_);
}

// ======================= tanh(P + pbias) + L2 normalize ======================
__global__ void __launch_bounds__(256) k_norm(float* __restrict__ out)
{
    const int b = blockIdx.x, tid = threadIdx.x;
    const float v = tanhf(SC_P[b * E_ + tid] + G_pb[tid]);
    float ss = v * v;
    const int lane = tid & 31, wid = tid >> 5;
#pragma unroll
    for (int o = 16; o; o >>= 1) ss += __shfl_xor_sync(0xffffffffu, ss, o);
    __shared__ float red[8];
    if (lane == 0) red[wid] = ss;
    __syncthreads();
    float tot = 0.f;
#pragma unroll
    for (int i = 0; i < 8; i++) tot += red[i];
    const float scale = 1.0f / fmaxf(sqrtf(tot), 1e-12f);
    out[b * E_ + tid] = v * scale;
}

// ======================= host ===============================================
extern "C" void kernel_launch(void* const* d_in, const int* in_sizes, int n_in,
                              void* d_out, int out_size)
{
    const int*   nodes  = (const int*)  d_in[0];
    const int*   n_mean = (const int*)  d_in[1];
    const int*   n_attn = (const int*)  d_in[2];
    const float* feat   = (const float*)d_in[3];
    const float* Wm = (const float*)d_in[4],  *bm = (const float*)d_in[5];
    const float* Wq = (const float*)d_in[6],  *bq = (const float*)d_in[7];
    const float* Wk = (const float*)d_in[8];  // bk cancels in softmax
    const float* Wv = (const float*)d_in[10], *bv = (const float*)d_in[11];
    const float* Wc = (const float*)d_in[12], *bc = (const float*)d_in[13];
    float* out = (float*)d_out;

    const dim3 ggrid(E_ / BNT, B_ / BMT, 1);   // (4, 64) = 256 CTAs

    // 1) prep: M = Wk Wq^T, Wpc = [Wv@Wc_top | Wm@Wc_bot]^T, c, pbias
    k_prep<<<dim3(8, 8, 4), 256>>>(Wm, Wv, Wc, Wk, Wq, bq, bv, bm, bc);

    // 2) t = feat[nodes] @ M^T  (self gather fused)
    k_tg<<<ggrid, 256>>>(nodes, feat);

    // 3) fused attention + mean aggregation -> ym = [y | m]
    k_attn<<<B_, 256>>>(n_attn, n_mean, feat);

    // 4) P = ym @ Wpc^T  (K = 512)
    k_pg<<<ggrid, 256>>>();

    // 5) out = L2-normalize(tanh(P + pbias))
    k_norm<<<B_, 256>>>(out);
}